// round 2
// baseline (speedup 1.0000x reference)
#include <cuda_runtime.h>
#include <math.h>

#define N_TOK   131072
#define D_DIM   192
#define K_CODE  128
#define GBLK    1024              // N_TOK / 128
#define SCALE_L 28.853900817779268f   // 20 / ln(2): Lc = cos*20*log2(e)

// ---------------- scratch (device globals; no runtime allocation) ------------
__device__ float g_Lc[(size_t)N_TOK * K_CODE];   // 67 MB: Lc[n][k]
__device__ float g_Rpart[GBLK * K_CODE];         // block partials for row sums
__device__ float g_rvec[K_CODE];                 // r1 then r2
__device__ float g_lr3[K_CODE];                  // log2(r3)
__device__ float g_memT[D_DIM * K_CODE];         // normalized mem bank, [d][k]
__device__ float g_hg[K_CODE * D_DIM];           // 0.5 * gated(mem_bank[k])
__device__ float g_memscale[K_CODE];

// ---------------- small helpers ---------------------------------------------
__device__ __forceinline__ float ex2f(float x) {
    float y; asm("ex2.approx.f32 %0, %1;" : "=f"(y) : "f"(x)); return y;
}
__device__ __forceinline__ unsigned long long pk2(float x) {
    unsigned long long r; asm("mov.b64 %0, {%1, %1};" : "=l"(r) : "f"(x)); return r;
}
__device__ __forceinline__ float2 up2(unsigned long long v) {
    float2 r; asm("mov.b64 {%0, %1}, %2;" : "=f"(r.x), "=f"(r.y) : "l"(v)); return r;
}
__device__ __forceinline__ void fma2(unsigned long long& a, unsigned long long x,
                                     unsigned long long m) {
    asm("fma.rn.f32x2 %0, %1, %2, %0;" : "+l"(a) : "l"(x), "l"(m));
}

// ---------------- K0: mem_bank norms + transposed normalized bank -----------
__global__ void kprep(const float* __restrict__ mem) {
    int tid = threadIdx.x;
    if (tid < K_CODE) {
        const float* row = mem + tid * D_DIM;
        float s = 0.f;
        #pragma unroll 8
        for (int d = 0; d < D_DIM; d++) s = fmaf(row[d], row[d], s);
        g_memscale[tid] = 1.0f / sqrtf(fmaxf(s, 1e-12f));
    }
    __syncthreads();
    for (int i = tid; i < D_DIM * K_CODE; i += blockDim.x) {
        int d = i >> 7, k = i & 127;
        g_memT[i] = mem[k * D_DIM + d] * g_memscale[k];
    }
}

// ---------------- K1: precompute 0.5*gated table for each of 128 codes ------
__global__ void kglu(const float* __restrict__ mem, const float* __restrict__ W,
                     const float* __restrict__ b) {
    __shared__ float a[D_DIM];
    int k = blockIdx.x, j = threadIdx.x;   // blockDim = 192
    for (int i = j; i < D_DIM; i += blockDim.x) a[i] = mem[k * D_DIM + i];
    __syncthreads();
    float av = b[j], ag = b[j + D_DIM];
    #pragma unroll 4
    for (int d = 0; d < D_DIM; d++) {
        float x = a[d];
        av = fmaf(x, W[d * 2 * D_DIM + j], av);
        ag = fmaf(x, W[d * 2 * D_DIM + D_DIM + j], ag);
    }
    float sig = 1.0f / (1.0f + expf(-ag));
    g_hg[k * D_DIM + j] = 0.5f * av * sig;
}

// ---------------- K2: similarity GEMM + token norms + r1 partials -----------
// Tile: 128 tokens x 128 codes per block, 128 threads, 8 tok x 16 codes/thread.
// Codes paired in f32x2; tokens scalar-broadcast (packed once per dd).
__global__ __launch_bounds__(128, 2) void kgemm(const float* __restrict__ proj) {
    __shared__ float sX[16][132];     // [dd][token], padded
    __shared__ float sM[16][128];     // [dd][code]
    __shared__ float sScale[128];
    __shared__ float sRed[16][128];

    int tid = threadIdx.x;
    int tx = tid & 7;                 // code group: codes tx*16 .. +15
    int ty = tid >> 3;                // token group: tokens ty*8 .. +7
    int t0 = blockIdx.x << 7;

    unsigned long long acc[8][8];
    #pragma unroll
    for (int i = 0; i < 8; i++)
        #pragma unroll
        for (int j = 0; j < 8; j++) acc[i][j] = 0ULL;
    float nacc = 0.f;

    for (int dc = 0; dc < 12; dc++) {
        if (dc) __syncthreads();
        // stage X chunk: sX[dd][t] = proj[t0+t][16*dc+dd]
        #pragma unroll
        for (int r = 0; r < 4; r++) {
            int f = tid + (r << 7);
            int tok = f >> 2, q = f & 3;
            float4 v = *(const float4*)(proj + (size_t)(t0 + tok) * D_DIM + dc * 16 + q * 4);
            sX[q * 4 + 0][tok] = v.x; sX[q * 4 + 1][tok] = v.y;
            sX[q * 4 + 2][tok] = v.z; sX[q * 4 + 3][tok] = v.w;
        }
        // stage M chunk (contiguous copy)
        #pragma unroll
        for (int r = 0; r < 4; r++) {
            int f = tid + (r << 7);
            ((float4*)sM)[f] = ((const float4*)(g_memT + dc * 2048))[f];
        }
        __syncthreads();
        // token norm partial (thread tid owns token tid)
        #pragma unroll
        for (int dd = 0; dd < 16; dd++) { float x = sX[dd][tid]; nacc = fmaf(x, x, nacc); }
        // compute
        #pragma unroll
        for (int dd = 0; dd < 16; dd++) {
            float4 xa = *(const float4*)&sX[dd][ty * 8];
            float4 xb = *(const float4*)&sX[dd][ty * 8 + 4];
            const ulonglong2* mp = (const ulonglong2*)&sM[dd][tx * 16];
            ulonglong2 m0 = mp[0], m1 = mp[1], m2v = mp[2], m3 = mp[3];
            unsigned long long mm[8] = { m0.x, m0.y, m1.x, m1.y, m2v.x, m2v.y, m3.x, m3.y };
            unsigned long long xx[8] = { pk2(xa.x), pk2(xa.y), pk2(xa.z), pk2(xa.w),
                                         pk2(xb.x), pk2(xb.y), pk2(xb.z), pk2(xb.w) };
            #pragma unroll
            for (int i = 0; i < 8; i++)
                #pragma unroll
                for (int j = 0; j < 8; j++) fma2(acc[i][j], xx[i], mm[j]);
        }
    }
    __syncthreads();
    sScale[tid] = SCALE_L / sqrtf(fmaxf(nacc, 1e-12f));
    __syncthreads();

    // epilogue: scale, store Lc, accumulate exp partials per code
    float ep[16];
    #pragma unroll
    for (int c = 0; c < 16; c++) ep[c] = 0.f;
    #pragma unroll
    for (int i = 0; i < 8; i++) {
        int tok = ty * 8 + i;
        float sc = sScale[tok];
        float o[16];
        #pragma unroll
        for (int j = 0; j < 8; j++) {
            float2 p = up2(acc[i][j]);
            o[2 * j]     = p.x * sc;
            o[2 * j + 1] = p.y * sc;
        }
        float4* dst = (float4*)(g_Lc + (size_t)(t0 + tok) * K_CODE + tx * 16);
        dst[0] = make_float4(o[0], o[1], o[2], o[3]);
        dst[1] = make_float4(o[4], o[5], o[6], o[7]);
        dst[2] = make_float4(o[8], o[9], o[10], o[11]);
        dst[3] = make_float4(o[12], o[13], o[14], o[15]);
        #pragma unroll
        for (int c = 0; c < 16; c++) ep[c] += ex2f(o[c]);
    }
    #pragma unroll
    for (int c = 0; c < 16; c++) sRed[ty][tx * 16 + c] = ep[c];
    __syncthreads();
    float s = 0.f;
    #pragma unroll
    for (int r = 0; r < 16; r++) s += sRed[r][tid];
    g_Rpart[blockIdx.x * K_CODE + tid] = s;
}

// ---------------- fixed-order reduction of block partials -------------------
__global__ void kreduce(int mode) {   // 1 block, 512 threads
    __shared__ float sm[4][K_CODE];
    int t = threadIdx.x, k = t & 127, p = t >> 7;
    float s = 0.f;
    #pragma unroll 8
    for (int i = 0; i < 256; i++) s += g_Rpart[(p * 256 + i) * K_CODE + k];
    sm[p][k] = s;
    __syncthreads();
    if (t < K_CODE) {
        float tot = ((sm[0][t] + sm[1][t]) + sm[2][t]) + sm[3][t];
        if (mode == 0) g_rvec[t] = 1.0f / tot;
        else           g_lr3[t]  = -log2f(tot);
    }
}

// ---------------- Sinkhorn pass: c = 1/(E·r) per token, accumulate E·c ------
__global__ void kpass() {   // grid 1024, block 256
    int lane = threadIdx.x & 31, w = threadIdx.x >> 5;
    int tok0 = (blockIdx.x * 8 + w) * 16;
    float r0 = g_rvec[lane * 4 + 0], r1 = g_rvec[lane * 4 + 1];
    float r2 = g_rvec[lane * 4 + 2], r3 = g_rvec[lane * 4 + 3];
    float a0 = 0.f, a1 = 0.f, a2 = 0.f, a3 = 0.f;
    #pragma unroll 2
    for (int i = 0; i < 16; i++) {
        float4 lc = *(const float4*)(g_Lc + (size_t)(tok0 + i) * K_CODE + lane * 4);
        float e0 = ex2f(lc.x), e1 = ex2f(lc.y), e2 = ex2f(lc.z), e3 = ex2f(lc.w);
        float t = fmaf(e0, r0, fmaf(e1, r1, fmaf(e2, r2, e3 * r3)));
        #pragma unroll
        for (int off = 16; off > 0; off >>= 1) t += __shfl_xor_sync(0xffffffffu, t, off);
        float c = 1.0f / t;
        a0 = fmaf(e0, c, a0); a1 = fmaf(e1, c, a1);
        a2 = fmaf(e2, c, a2); a3 = fmaf(e3, c, a3);
    }
    __shared__ float sm[8][K_CODE];
    sm[w][lane * 4 + 0] = a0; sm[w][lane * 4 + 1] = a1;
    sm[w][lane * 4 + 2] = a2; sm[w][lane * 4 + 3] = a3;
    __syncthreads();
    int t = threadIdx.x;
    if (t < K_CODE) {
        float s = 0.f;
        #pragma unroll
        for (int ww = 0; ww < 8; ww++) s += sm[ww][t];
        g_Rpart[blockIdx.x * K_CODE + t] = s;
    }
}

// ---------------- argmax + gather + GLU output ------------------------------
__global__ void kfinal(const float* __restrict__ proj, float* __restrict__ out) {
    int lane = threadIdx.x & 31, w = threadIdx.x >> 5;
    int tok0 = (blockIdx.x * 8 + w) * 16;
    float l0 = g_lr3[lane * 4 + 0], l1 = g_lr3[lane * 4 + 1];
    float l2 = g_lr3[lane * 4 + 2], l3 = g_lr3[lane * 4 + 3];
    for (int i = 0; i < 16; i++) {
        int n = tok0 + i;
        float4 lc = *(const float4*)(g_Lc + (size_t)n * K_CODE + lane * 4);
        float v0 = lc.x + l0, v1 = lc.y + l1, v2 = lc.z + l2, v3 = lc.w + l3;
        float bv = v0; int bk = lane * 4;
        if (v1 > bv) { bv = v1; bk = lane * 4 + 1; }
        if (v2 > bv) { bv = v2; bk = lane * 4 + 2; }
        if (v3 > bv) { bv = v3; bk = lane * 4 + 3; }
        #pragma unroll
        for (int off = 16; off > 0; off >>= 1) {
            float ov = __shfl_xor_sync(0xffffffffu, bv, off);
            int   ok = __shfl_xor_sync(0xffffffffu, bk, off);
            if (ov > bv || (ov == bv && ok < bk)) { bv = ov; bk = ok; }
        }
        const float* hg = g_hg + bk * D_DIM;
        size_t base = (size_t)n * D_DIM;
        #pragma unroll
        for (int jj = 0; jj < 3; jj++) {
            int off2 = lane * 2 + jj * 64;
            float2 p = *(const float2*)(proj + base + off2);
            float2 h = *(const float2*)(hg + off2);
            float2 o;
            o.x = fmaf(0.5f, p.x, h.x);
            o.y = fmaf(0.5f, p.y, h.y);
            *(float2*)(out + base + off2) = o;
        }
    }
}

// ---------------- launch -----------------------------------------------------
extern "C" void kernel_launch(void* const* d_in, const int* in_sizes, int n_in,
                              void* d_out, int out_size) {
    const float* proj = (const float*)d_in[0];
    const float* mem  = (const float*)d_in[1];
    const float* W    = (const float*)d_in[2];
    const float* b    = (const float*)d_in[3];
    float* out = (float*)d_out;

    kprep<<<1, 256>>>(mem);
    kglu<<<K_CODE, D_DIM>>>(mem, W, b);
    kgemm<<<GBLK, 128>>>(proj);
    kreduce<<<1, 512>>>(0);        // r1
    kpass<<<GBLK, 256>>>();        // c1, partials for r2
    kreduce<<<1, 512>>>(0);        // r2
    kpass<<<GBLK, 256>>>();        // c2, partials for r3
    kreduce<<<1, 512>>>(1);        // log2(r3)
    kfinal<<<GBLK, 256>>>(proj, out);
}

// round 5
// speedup vs baseline: 1.3847x; 1.3847x over previous
#include <cuda_runtime.h>
#include <math.h>

#define N_TOK   131072
#define D_DIM   192
#define K_CODE  128
#define GBLK    1024              // N_TOK / 128
#define SCALE_L 28.853900817779268f   // 20 / ln(2): Lc = cos*20*log2(e)

// ---------------- scratch (device globals; no runtime allocation) ------------
__device__ float g_Lc[(size_t)N_TOK * K_CODE];   // 67 MB: Lc[n][k]
__device__ float g_Rpart[GBLK * K_CODE];         // block partials, [block][k] (R2 layout)
__device__ float g_rvec[K_CODE];                 // r1 then r2
__device__ float g_lr3[K_CODE];                  // log2(r3)
__device__ float g_memT[D_DIM * K_CODE];         // normalized mem bank, [d][k]
__device__ float g_hg[K_CODE * D_DIM];           // 0.5 * gated(mem_bank[k])

// ---------------- small helpers ---------------------------------------------
__device__ __forceinline__ float ex2f(float x) {
    float y; asm("ex2.approx.f32 %0, %1;" : "=f"(y) : "f"(x)); return y;
}
__device__ __forceinline__ unsigned long long pk2(float x) {
    unsigned long long r; asm("mov.b64 %0, {%1, %1};" : "=l"(r) : "f"(x)); return r;
}
__device__ __forceinline__ float2 up2(unsigned long long v) {
    float2 r; asm("mov.b64 {%0, %1}, %2;" : "=f"(r.x), "=f"(r.y) : "l"(v)); return r;
}
__device__ __forceinline__ void fma2(unsigned long long& a, unsigned long long x,
                                     unsigned long long m) {
    asm("fma.rn.f32x2 %0, %1, %2, %0;" : "+l"(a) : "l"(x), "l"(m));
}

// ---------------- K0: per-code norm + transposed bank + GLU table (fused) ---
// grid 128 (one block per code), block 192. Norm chain = R2's sequential order.
__global__ void kprep(const float* __restrict__ mem, const float* __restrict__ W,
                      const float* __restrict__ b) {
    __shared__ float a[D_DIM];
    __shared__ float s_scale;
    int k = blockIdx.x, j = threadIdx.x;
    a[j] = mem[k * D_DIM + j];
    __syncthreads();
    if (j == 0) {
        float s = 0.f;
        #pragma unroll 8
        for (int d = 0; d < D_DIM; d++) s = fmaf(a[d], a[d], s);   // R2 bit order
        s_scale = 1.0f / sqrtf(fmaxf(s, 1e-12f));
    }
    __syncthreads();
    g_memT[j * K_CODE + k] = a[j] * s_scale;     // transposed normalized bank
    // GLU table for this code (does not feed argmax)
    float av = b[j], ag = b[j + D_DIM];
    #pragma unroll 4
    for (int d = 0; d < D_DIM; d++) {
        float xd = a[d];
        av = fmaf(xd, W[d * 2 * D_DIM + j], av);
        ag = fmaf(xd, W[d * 2 * D_DIM + D_DIM + j], ag);
    }
    float sig = 1.0f / (1.0f + expf(-ag));
    g_hg[k * D_DIM + j] = 0.5f * av * sig;
}

// ---------------- K1: similarity GEMM + token norms + r1 partials -----------
// 128 tokens x 128 codes per block, 256 threads, 8 tok x 8 codes/thread.
// All FP chains bit-identical to the R2 (128-thread) version.
__global__ __launch_bounds__(256, 2) void kgemm(const float* __restrict__ proj) {
    __shared__ float sX[16][132];     // [dd][token], padded
    __shared__ float sM[16][128];     // [dd][code]
    __shared__ float sScale[128];
    __shared__ float sRed[16][128];

    int tid = threadIdx.x;
    int tx = tid & 15;                // code group: codes tx*8 .. +7
    int ty = tid >> 4;                // token group: tokens ty*8 .. +7
    int t0 = blockIdx.x << 7;

    unsigned long long acc[8][4];
    #pragma unroll
    for (int i = 0; i < 8; i++)
        #pragma unroll
        for (int j = 0; j < 4; j++) acc[i][j] = 0ULL;
    float nacc = 0.f;

    for (int dc = 0; dc < 12; dc++) {
        if (dc) __syncthreads();
        // stage X chunk: sX[dd][t] = proj[t0+t][16*dc+dd]; 512 float4, 2/thread
        #pragma unroll
        for (int r = 0; r < 2; r++) {
            int f = tid + (r << 8);
            int tok = f >> 2, q = f & 3;
            float4 v = *(const float4*)(proj + (size_t)(t0 + tok) * D_DIM + dc * 16 + q * 4);
            sX[q * 4 + 0][tok] = v.x; sX[q * 4 + 1][tok] = v.y;
            sX[q * 4 + 2][tok] = v.z; sX[q * 4 + 3][tok] = v.w;
        }
        // stage M chunk (contiguous copy)
        #pragma unroll
        for (int r = 0; r < 2; r++) {
            int f = tid + (r << 8);
            ((float4*)sM)[f] = ((const float4*)(g_memT + dc * 2048))[f];
        }
        __syncthreads();
        // token norm partial: thread tid (<128) owns token tid — R2 bit order
        if (tid < 128) {
            #pragma unroll
            for (int dd = 0; dd < 16; dd++) { float x = sX[dd][tid]; nacc = fmaf(x, x, nacc); }
        }
        // compute 8x8 per thread, codes paired in f32x2 (same per-pair chain as R2)
        #pragma unroll
        for (int dd = 0; dd < 16; dd++) {
            float4 xa = *(const float4*)&sX[dd][ty * 8];
            float4 xb = *(const float4*)&sX[dd][ty * 8 + 4];
            ulonglong2 m0 = ((const ulonglong2*)&sM[dd][tx * 8])[0];
            ulonglong2 m1 = ((const ulonglong2*)&sM[dd][tx * 8])[1];
            unsigned long long mm[4] = { m0.x, m0.y, m1.x, m1.y };
            unsigned long long xx[8] = { pk2(xa.x), pk2(xa.y), pk2(xa.z), pk2(xa.w),
                                         pk2(xb.x), pk2(xb.y), pk2(xb.z), pk2(xb.w) };
            #pragma unroll
            for (int i = 0; i < 8; i++)
                #pragma unroll
                for (int j = 0; j < 4; j++) fma2(acc[i][j], xx[i], mm[j]);
        }
    }
    __syncthreads();
    if (tid < 128) sScale[tid] = SCALE_L / sqrtf(fmaxf(nacc, 1e-12f));
    __syncthreads();

    // epilogue: scale, store Lc, accumulate exp partials per code
    float ep[8];
    #pragma unroll
    for (int c = 0; c < 8; c++) ep[c] = 0.f;
    #pragma unroll
    for (int i = 0; i < 8; i++) {
        int tok = ty * 8 + i;
        float sc = sScale[tok];
        float o[8];
        #pragma unroll
        for (int j = 0; j < 4; j++) {
            float2 p = up2(acc[i][j]);
            o[2 * j]     = p.x * sc;
            o[2 * j + 1] = p.y * sc;
        }
        float4* dst = (float4*)(g_Lc + (size_t)(t0 + tok) * K_CODE + tx * 8);
        dst[0] = make_float4(o[0], o[1], o[2], o[3]);
        dst[1] = make_float4(o[4], o[5], o[6], o[7]);
        #pragma unroll
        for (int c = 0; c < 8; c++) ep[c] += ex2f(o[c]);
    }
    #pragma unroll
    for (int c = 0; c < 8; c++) sRed[ty][tx * 8 + c] = ep[c];
    __syncthreads();
    if (tid < 128) {
        float s = 0.f;
        #pragma unroll
        for (int r = 0; r < 16; r++) s += sRed[r][tid];   // tokens 0..127 ascending (R2 order)
        g_Rpart[blockIdx.x * K_CODE + tid] = s;
    }
}

// ---------------- reduction: R2's exact summation order, 512-way parallel ---
// grid 128 (one block per code), block 32 (lanes 0..3 active).
// lane p sums partials (p*256 .. p*256+255) sequentially; combine ((q0+q1)+q2)+q3.
__global__ void kreduce(int mode) {
    __shared__ float sm[4];
    int k = blockIdx.x, lane = threadIdx.x;
    if (lane < 4) {
        float s = 0.f;
        const float* p = g_Rpart + (size_t)(lane * 256) * K_CODE + k;
        #pragma unroll 8
        for (int i = 0; i < 256; i++) s += p[(size_t)i * K_CODE];
        sm[lane] = s;
    }
    __syncthreads();
    if (lane == 0) {
        float tot = ((sm[0] + sm[1]) + sm[2]) + sm[3];   // R2 combine order
        if (mode == 0) g_rvec[k] = 1.0f / tot;
        else           g_lr3[k]  = -log2f(tot);
    }
}

// ---------------- Sinkhorn pass: c = 1/(E·r) per token, accumulate E·c ------
// Verbatim R2.
__global__ void kpass() {   // grid 1024, block 256
    int lane = threadIdx.x & 31, w = threadIdx.x >> 5;
    int tok0 = (blockIdx.x * 8 + w) * 16;
    float r0 = g_rvec[lane * 4 + 0], r1 = g_rvec[lane * 4 + 1];
    float r2 = g_rvec[lane * 4 + 2], r3 = g_rvec[lane * 4 + 3];
    float a0 = 0.f, a1 = 0.f, a2 = 0.f, a3 = 0.f;
    #pragma unroll 2
    for (int i = 0; i < 16; i++) {
        float4 lc = *(const float4*)(g_Lc + (size_t)(tok0 + i) * K_CODE + lane * 4);
        float e0 = ex2f(lc.x), e1 = ex2f(lc.y), e2 = ex2f(lc.z), e3 = ex2f(lc.w);
        float t = fmaf(e0, r0, fmaf(e1, r1, fmaf(e2, r2, e3 * r3)));
        #pragma unroll
        for (int off = 16; off > 0; off >>= 1) t += __shfl_xor_sync(0xffffffffu, t, off);
        float c = 1.0f / t;
        a0 = fmaf(e0, c, a0); a1 = fmaf(e1, c, a1);
        a2 = fmaf(e2, c, a2); a3 = fmaf(e3, c, a3);
    }
    __shared__ float sm[8][K_CODE];
    sm[w][lane * 4 + 0] = a0; sm[w][lane * 4 + 1] = a1;
    sm[w][lane * 4 + 2] = a2; sm[w][lane * 4 + 3] = a3;
    __syncthreads();
    int t = threadIdx.x;
    if (t < K_CODE) {
        float s = 0.f;
        #pragma unroll
        for (int ww = 0; ww < 8; ww++) s += sm[ww][t];
        g_Rpart[blockIdx.x * K_CODE + t] = s;
    }
}

// ---------------- argmax + gather + GLU output ------------------------------
__global__ void kfinal(const float* __restrict__ proj, float* __restrict__ out) {
    int lane = threadIdx.x & 31, w = threadIdx.x >> 5;
    int tok0 = (blockIdx.x * 8 + w) * 16;
    float l0 = g_lr3[lane * 4 + 0], l1 = g_lr3[lane * 4 + 1];
    float l2 = g_lr3[lane * 4 + 2], l3 = g_lr3[lane * 4 + 3];
    for (int i = 0; i < 16; i++) {
        int n = tok0 + i;
        float4 lc = *(const float4*)(g_Lc + (size_t)n * K_CODE + lane * 4);
        float v0 = lc.x + l0, v1 = lc.y + l1, v2 = lc.z + l2, v3 = lc.w + l3;
        // lane-local best (ties -> lowest k)
        float lbv = v0; int lbk = lane * 4;
        if (v1 > lbv) { lbv = v1; lbk = lane * 4 + 1; }
        if (v2 > lbv) { lbv = v2; lbk = lane * 4 + 2; }
        if (v3 > lbv) { lbv = v3; lbk = lane * 4 + 3; }
        // warp max (5 shfls), then lowest-lane (= lowest k) tie-break via ballot
        float bv = lbv;
        #pragma unroll
        for (int off = 16; off > 0; off >>= 1)
            bv = fmaxf(bv, __shfl_xor_sync(0xffffffffu, bv, off));
        unsigned mask = __ballot_sync(0xffffffffu, lbv == bv);
        int src = __ffs(mask) - 1;
        int bk = __shfl_sync(0xffffffffu, lbk, src);

        const float* hg = g_hg + bk * D_DIM;
        size_t base = (size_t)n * D_DIM;
        #pragma unroll
        for (int jj = 0; jj < 3; jj++) {
            int off2 = lane * 2 + jj * 64;
            float2 p = *(const float2*)(proj + base + off2);
            float2 h = *(const float2*)(hg + off2);
            float2 o;
            o.x = fmaf(0.5f, p.x, h.x);
            o.y = fmaf(0.5f, p.y, h.y);
            *(float2*)(out + base + off2) = o;
        }
    }
}

// ---------------- launch -----------------------------------------------------
extern "C" void kernel_launch(void* const* d_in, const int* in_sizes, int n_in,
                              void* d_out, int out_size) {
    const float* proj = (const float*)d_in[0];
    const float* mem  = (const float*)d_in[1];
    const float* W    = (const float*)d_in[2];
    const float* b    = (const float*)d_in[3];
    float* out = (float*)d_out;

    kprep<<<K_CODE, D_DIM>>>(mem, W, b);
    kgemm<<<GBLK, 256>>>(proj);
    kreduce<<<K_CODE, 32>>>(0);    // r1
    kpass<<<GBLK, 256>>>();        // c1, partials for r2
    kreduce<<<K_CODE, 32>>>(0);    // r2
    kpass<<<GBLK, 256>>>();        // c2, partials for r3
    kreduce<<<K_CODE, 32>>>(1);    // log2(r3)
    kfinal<<<GBLK, 256>>>(proj, out);
}

// round 6
// speedup vs baseline: 1.4013x; 1.0120x over previous
#include <cuda_runtime.h>
#include <math.h>

#define N_TOK   131072
#define D_DIM   192
#define K_CODE  128
#define GBLK    1024              // N_TOK / 128
#define SCALE_L 28.853900817779268f   // 20 / ln(2): Lc = cos*20*log2(e)

// ---------------- scratch (device globals; no runtime allocation) ------------
__device__ float g_Lc[(size_t)N_TOK * K_CODE];   // 67 MB: Lc[n][k]
__device__ float g_Rpart[GBLK * K_CODE];         // block partials, [block][k]
__device__ float g_rvec[K_CODE];                 // r1 then r2
__device__ float g_lr3[K_CODE];                  // log2(r3)
__device__ float g_memT[D_DIM * K_CODE];         // normalized mem bank, [d][k]
__device__ float g_hg[K_CODE * D_DIM];           // 0.5 * gated(mem_bank[k])

// ---------------- small helpers ---------------------------------------------
__device__ __forceinline__ float ex2f(float x) {
    float y; asm("ex2.approx.f32 %0, %1;" : "=f"(y) : "f"(x)); return y;
}
__device__ __forceinline__ unsigned long long pk2(float x) {
    unsigned long long r; asm("mov.b64 %0, {%1, %1};" : "=l"(r) : "f"(x)); return r;
}
__device__ __forceinline__ float2 up2(unsigned long long v) {
    float2 r; asm("mov.b64 {%0, %1}, %2;" : "=f"(r.x), "=f"(r.y) : "l"(v)); return r;
}
__device__ __forceinline__ void fma2(unsigned long long& a, unsigned long long x,
                                     unsigned long long m) {
    asm("fma.rn.f32x2 %0, %1, %2, %0;" : "+l"(a) : "l"(x), "l"(m));
}

// ---------------- K0: per-code norm + transposed bank + GLU table (fused) ---
__global__ void kprep(const float* __restrict__ mem, const float* __restrict__ W,
                      const float* __restrict__ b) {
    __shared__ float a[D_DIM];
    __shared__ float s_scale;
    int k = blockIdx.x, j = threadIdx.x;
    a[j] = mem[k * D_DIM + j];
    __syncthreads();
    if (j == 0) {
        float s = 0.f;
        #pragma unroll 8
        for (int d = 0; d < D_DIM; d++) s = fmaf(a[d], a[d], s);   // R2 bit order
        s_scale = 1.0f / sqrtf(fmaxf(s, 1e-12f));
    }
    __syncthreads();
    g_memT[j * K_CODE + k] = a[j] * s_scale;
    float av = b[j], ag = b[j + D_DIM];
    #pragma unroll 4
    for (int d = 0; d < D_DIM; d++) {
        float xd = a[d];
        av = fmaf(xd, W[d * 2 * D_DIM + j], av);
        ag = fmaf(xd, W[d * 2 * D_DIM + D_DIM + j], ag);
    }
    float sig = 1.0f / (1.0f + expf(-ag));
    g_hg[k * D_DIM + j] = 0.5f * av * sig;
}

// ---------------- K1: similarity GEMM, double-buffered ----------------------
// 128 tokens x 128 codes per block, 256 threads, 8 tok x 8 codes/thread.
// FP chains bit-identical to R5; only smem ping-pong + register prefetch added.
__global__ __launch_bounds__(256, 2) void kgemm(const float* __restrict__ proj) {
    __shared__ float sX[2][16][132];     // [buf][dd][token], padded
    __shared__ float sM[2][16][128];     // [buf][dd][code]
    __shared__ float sScale[128];
    __shared__ float sRed[16][128];

    int tid = threadIdx.x;
    int tx = tid & 15;                // code group: codes tx*8 .. +7
    int ty = tid >> 4;                // token group: tokens ty*8 .. +7
    int t0 = blockIdx.x << 7;
    int tokA = tid >> 2, q = tid & 3; // X staging slots (r=0)
    int tokB = tokA + 64;             //              (r=1)

    unsigned long long acc[8][4];
    #pragma unroll
    for (int i = 0; i < 8; i++)
        #pragma unroll
        for (int j = 0; j < 4; j++) acc[i][j] = 0ULL;
    float nacc = 0.f;

    // prologue: stage chunk 0 into buffer 0
    {
        float4 xA = *(const float4*)(proj + (size_t)(t0 + tokA) * D_DIM + q * 4);
        float4 xB = *(const float4*)(proj + (size_t)(t0 + tokB) * D_DIM + q * 4);
        float4 mA = ((const float4*)g_memT)[tid];
        float4 mB = ((const float4*)g_memT)[tid + 256];
        sX[0][q * 4 + 0][tokA] = xA.x; sX[0][q * 4 + 1][tokA] = xA.y;
        sX[0][q * 4 + 2][tokA] = xA.z; sX[0][q * 4 + 3][tokA] = xA.w;
        sX[0][q * 4 + 0][tokB] = xB.x; sX[0][q * 4 + 1][tokB] = xB.y;
        sX[0][q * 4 + 2][tokB] = xB.z; sX[0][q * 4 + 3][tokB] = xB.w;
        ((float4*)sM[0])[tid] = mA;
        ((float4*)sM[0])[tid + 256] = mB;
    }
    __syncthreads();

    for (int dc = 0; dc < 12; dc++) {
        int cur = dc & 1, nxt = cur ^ 1;
        // prefetch chunk dc+1 into registers (latency overlapped with compute)
        float4 pxA, pxB, pmA, pmB;
        if (dc < 11) {
            pxA = *(const float4*)(proj + (size_t)(t0 + tokA) * D_DIM + (dc + 1) * 16 + q * 4);
            pxB = *(const float4*)(proj + (size_t)(t0 + tokB) * D_DIM + (dc + 1) * 16 + q * 4);
            pmA = ((const float4*)(g_memT + (dc + 1) * 2048))[tid];
            pmB = ((const float4*)(g_memT + (dc + 1) * 2048))[tid + 256];
        }
        // token norm partial: thread tid (<128) owns token tid — R2 bit order
        if (tid < 128) {
            #pragma unroll
            for (int dd = 0; dd < 16; dd++) { float x = sX[cur][dd][tid]; nacc = fmaf(x, x, nacc); }
        }
        // compute 8x8 per thread, codes paired in f32x2 (same per-pair chain)
        #pragma unroll
        for (int dd = 0; dd < 16; dd++) {
            float4 xa = *(const float4*)&sX[cur][dd][ty * 8];
            float4 xb = *(const float4*)&sX[cur][dd][ty * 8 + 4];
            ulonglong2 m0 = ((const ulonglong2*)&sM[cur][dd][tx * 8])[0];
            ulonglong2 m1 = ((const ulonglong2*)&sM[cur][dd][tx * 8])[1];
            unsigned long long mm[4] = { m0.x, m0.y, m1.x, m1.y };
            unsigned long long xx[8] = { pk2(xa.x), pk2(xa.y), pk2(xa.z), pk2(xa.w),
                                         pk2(xb.x), pk2(xb.y), pk2(xb.z), pk2(xb.w) };
            #pragma unroll
            for (int i = 0; i < 8; i++)
                #pragma unroll
                for (int j = 0; j < 4; j++) fma2(acc[i][j], xx[i], mm[j]);
        }
        if (dc < 11) {
            sX[nxt][q * 4 + 0][tokA] = pxA.x; sX[nxt][q * 4 + 1][tokA] = pxA.y;
            sX[nxt][q * 4 + 2][tokA] = pxA.z; sX[nxt][q * 4 + 3][tokA] = pxA.w;
            sX[nxt][q * 4 + 0][tokB] = pxB.x; sX[nxt][q * 4 + 1][tokB] = pxB.y;
            sX[nxt][q * 4 + 2][tokB] = pxB.z; sX[nxt][q * 4 + 3][tokB] = pxB.w;
            ((float4*)sM[nxt])[tid] = pmA;
            ((float4*)sM[nxt])[tid + 256] = pmB;
            __syncthreads();
        }
    }
    __syncthreads();
    if (tid < 128) sScale[tid] = SCALE_L / sqrtf(fmaxf(nacc, 1e-12f));
    __syncthreads();

    // epilogue: scale, store Lc, accumulate exp partials per code
    float ep[8];
    #pragma unroll
    for (int c = 0; c < 8; c++) ep[c] = 0.f;
    #pragma unroll
    for (int i = 0; i < 8; i++) {
        int tok = ty * 8 + i;
        float sc = sScale[tok];
        float o[8];
        #pragma unroll
        for (int j = 0; j < 4; j++) {
            float2 p = up2(acc[i][j]);
            o[2 * j]     = p.x * sc;
            o[2 * j + 1] = p.y * sc;
        }
        float4* dst = (float4*)(g_Lc + (size_t)(t0 + tok) * K_CODE + tx * 8);
        dst[0] = make_float4(o[0], o[1], o[2], o[3]);
        dst[1] = make_float4(o[4], o[5], o[6], o[7]);
        #pragma unroll
        for (int c = 0; c < 8; c++) ep[c] += ex2f(o[c]);
    }
    #pragma unroll
    for (int c = 0; c < 8; c++) sRed[ty][tx * 8 + c] = ep[c];
    __syncthreads();
    if (tid < 128) {
        float s = 0.f;
        #pragma unroll
        for (int r = 0; r < 16; r++) s += sRed[r][tid];   // tokens 0..127 ascending
        g_Rpart[blockIdx.x * K_CODE + tid] = s;
    }
}

// ---------------- reduction: R2's exact summation order, parallel -----------
__global__ void kreduce(int mode) {   // grid 128, block 32
    __shared__ float sm[4];
    int k = blockIdx.x, lane = threadIdx.x;
    if (lane < 4) {
        float s = 0.f;
        const float* p = g_Rpart + (size_t)(lane * 256) * K_CODE + k;
        #pragma unroll 8
        for (int i = 0; i < 256; i++) s += p[(size_t)i * K_CODE];
        sm[lane] = s;
    }
    __syncthreads();
    if (lane == 0) {
        float tot = ((sm[0] + sm[1]) + sm[2]) + sm[3];
        if (mode == 0) g_rvec[k] = 1.0f / tot;
        else           g_lr3[k]  = -log2f(tot);
    }
}

// ---------------- Sinkhorn pass, 4-token batched butterflies ----------------
// Bit-identical chains to R5 kpass; the 4 butterflies now pipeline.
__global__ void kpass() {   // grid 1024, block 256
    int lane = threadIdx.x & 31, w = threadIdx.x >> 5;
    int tok0 = (blockIdx.x * 8 + w) * 16;
    float r0 = g_rvec[lane * 4 + 0], r1 = g_rvec[lane * 4 + 1];
    float r2 = g_rvec[lane * 4 + 2], r3 = g_rvec[lane * 4 + 3];
    float a0 = 0.f, a1 = 0.f, a2 = 0.f, a3 = 0.f;
    for (int g = 0; g < 4; g++) {
        float e[4][4], t[4];
        #pragma unroll
        for (int j = 0; j < 4; j++) {
            float4 lc = *(const float4*)(g_Lc + (size_t)(tok0 + g * 4 + j) * K_CODE + lane * 4);
            e[j][0] = ex2f(lc.x); e[j][1] = ex2f(lc.y);
            e[j][2] = ex2f(lc.z); e[j][3] = ex2f(lc.w);
            t[j] = fmaf(e[j][0], r0, fmaf(e[j][1], r1, fmaf(e[j][2], r2, e[j][3] * r3)));
        }
        #pragma unroll
        for (int off = 16; off > 0; off >>= 1) {
            t[0] += __shfl_xor_sync(0xffffffffu, t[0], off);
            t[1] += __shfl_xor_sync(0xffffffffu, t[1], off);
            t[2] += __shfl_xor_sync(0xffffffffu, t[2], off);
            t[3] += __shfl_xor_sync(0xffffffffu, t[3], off);
        }
        #pragma unroll
        for (int j = 0; j < 4; j++) {      // ascending token order (bit order kept)
            float c = 1.0f / t[j];
            a0 = fmaf(e[j][0], c, a0); a1 = fmaf(e[j][1], c, a1);
            a2 = fmaf(e[j][2], c, a2); a3 = fmaf(e[j][3], c, a3);
        }
    }
    __shared__ float sm[8][K_CODE];
    sm[w][lane * 4 + 0] = a0; sm[w][lane * 4 + 1] = a1;
    sm[w][lane * 4 + 2] = a2; sm[w][lane * 4 + 3] = a3;
    __syncthreads();
    int t = threadIdx.x;
    if (t < K_CODE) {
        float s = 0.f;
        #pragma unroll
        for (int ww = 0; ww < 8; ww++) s += sm[ww][t];
        g_Rpart[blockIdx.x * K_CODE + t] = s;
    }
}

// ---------------- argmax + gather + GLU output, 4-token batched -------------
__global__ void kfinal(const float* __restrict__ proj, float* __restrict__ out) {
    int lane = threadIdx.x & 31, w = threadIdx.x >> 5;
    int tok0 = (blockIdx.x * 8 + w) * 16;
    float l0 = g_lr3[lane * 4 + 0], l1 = g_lr3[lane * 4 + 1];
    float l2 = g_lr3[lane * 4 + 2], l3 = g_lr3[lane * 4 + 3];
    for (int g = 0; g < 4; g++) {
        float lbv[4], bv[4];
        int lbk[4], bk[4];
        #pragma unroll
        for (int j = 0; j < 4; j++) {
            int n = tok0 + g * 4 + j;
            float4 lc = *(const float4*)(g_Lc + (size_t)n * K_CODE + lane * 4);
            float v0 = lc.x + l0, v1 = lc.y + l1, v2 = lc.z + l2, v3 = lc.w + l3;
            float b_ = v0; int k_ = lane * 4;
            if (v1 > b_) { b_ = v1; k_ = lane * 4 + 1; }
            if (v2 > b_) { b_ = v2; k_ = lane * 4 + 2; }
            if (v3 > b_) { b_ = v3; k_ = lane * 4 + 3; }
            lbv[j] = b_; lbk[j] = k_; bv[j] = b_;
        }
        #pragma unroll
        for (int off = 16; off > 0; off >>= 1) {
            bv[0] = fmaxf(bv[0], __shfl_xor_sync(0xffffffffu, bv[0], off));
            bv[1] = fmaxf(bv[1], __shfl_xor_sync(0xffffffffu, bv[1], off));
            bv[2] = fmaxf(bv[2], __shfl_xor_sync(0xffffffffu, bv[2], off));
            bv[3] = fmaxf(bv[3], __shfl_xor_sync(0xffffffffu, bv[3], off));
        }
        #pragma unroll
        for (int j = 0; j < 4; j++) {
            unsigned mask = __ballot_sync(0xffffffffu, lbv[j] == bv[j]);
            int src = __ffs(mask) - 1;
            bk[j] = __shfl_sync(0xffffffffu, lbk[j], src);
        }
        #pragma unroll
        for (int j = 0; j < 4; j++) {
            int n = tok0 + g * 4 + j;
            const float* hg = g_hg + bk[j] * D_DIM;
            size_t base = (size_t)n * D_DIM;
            #pragma unroll
            for (int jj = 0; jj < 3; jj++) {
                int off2 = lane * 2 + jj * 64;
                float2 p = *(const float2*)(proj + base + off2);
                float2 h = *(const float2*)(hg + off2);
                float2 o;
                o.x = fmaf(0.5f, p.x, h.x);
                o.y = fmaf(0.5f, p.y, h.y);
                *(float2*)(out + base + off2) = o;
            }
        }
    }
}

// ---------------- launch -----------------------------------------------------
extern "C" void kernel_launch(void* const* d_in, const int* in_sizes, int n_in,
                              void* d_out, int out_size) {
    const float* proj = (const float*)d_in[0];
    const float* mem  = (const float*)d_in[1];
    const float* W    = (const float*)d_in[2];
    const float* b    = (const float*)d_in[3];
    float* out = (float*)d_out;

    kprep<<<K_CODE, D_DIM>>>(mem, W, b);
    kgemm<<<GBLK, 256>>>(proj);
    kreduce<<<K_CODE, 32>>>(0);    // r1
    kpass<<<GBLK, 256>>>();        // c1, partials for r2
    kreduce<<<K_CODE, 32>>>(0);    // r2
    kpass<<<GBLK, 256>>>();        // c2, partials for r3
    kreduce<<<K_CODE, 32>>>(1);    // log2(r3)
    kfinal<<<GBLK, 256>>>(proj, out);
}